// round 1
// baseline (speedup 1.0000x reference)
#include <cuda_runtime.h>
#include <cuda_bf16.h>

// PairwisePotential1: out[b,c,y,x] = w1[c,y,x] * first/9 + w2[c,y,x] * (4+4*sqrt2)/9
// where, with (Y,X) = (y-1,x-1) and zero padding outside [0,128):
//   first = sum_{i,j in {0,1,2}} exp(-0.5*(v(Y,X)-v(Y+i,X+j))^2 - 0.5*d(i,j))
//   d component: 0 for index 0, 1 for indices 1 and 2; d = sqrt(di^2+dj^2).
// The (0,0) term is exactly 1. d-weights folded into the exp2 argument.

#define S 128
#define SS (S * S)

__global__ __launch_bounds__(256) void pp_kernel(
    const float* __restrict__ x,
    const float* __restrict__ w1,
    const float* __restrict__ w2,
    float* __restrict__ out)
{
    int idx = blockIdx.x * blockDim.x + threadIdx.x;  // one thread per output element
    int xc = idx & (S - 1);
    int y  = (idx >> 7) & (S - 1);
    int bc = idx >> 14;            // b*C + c
    int c  = bc & 63;

    const float* __restrict__ xb = x + (size_t)bc * SS;

    // Load 3x3 window rooted at (y-1, x-1) in original coords, zero OOB.
    float v[3][3];
#pragma unroll
    for (int i = 0; i < 3; i++) {
        int ry = y - 1 + i;
        bool okY = (ry >= 0) & (ry < S);
#pragma unroll
        for (int j = 0; j < 3; j++) {
            int rx = xc - 1 + j;
            bool ok = okY & (rx >= 0) & (rx < S);
            v[i][j] = ok ? __ldg(&xb[ry * S + rx]) : 0.0f;
        }
    }

    const float cv = v[0][0];

    // K = -0.5 * log2(e); exponent offsets for d=1 and d=sqrt(2)
    const float K  = -0.5f * 1.44269504088896340736f;
    const float L1 = K * 1.0f;
    const float L2 = K * 1.41421356237309504880f;

    float acc = 1.0f;  // (0,0) term
    {
        float d01 = cv - v[0][1];
        float d02 = cv - v[0][2];
        float d10 = cv - v[1][0];
        float d20 = cv - v[2][0];
        float d11 = cv - v[1][1];
        float d12 = cv - v[1][2];
        float d21 = cv - v[2][1];
        float d22 = cv - v[2][2];
        acc += exp2f(fmaf(d01 * d01, K, L1));
        acc += exp2f(fmaf(d02 * d02, K, L1));
        acc += exp2f(fmaf(d10 * d10, K, L1));
        acc += exp2f(fmaf(d20 * d20, K, L1));
        acc += exp2f(fmaf(d11 * d11, K, L2));
        acc += exp2f(fmaf(d12 * d12, K, L2));
        acc += exp2f(fmaf(d21 * d21, K, L2));
        acc += exp2f(fmaf(d22 * d22, K, L2));
    }

    const float SECOND = (4.0f + 4.0f * 1.41421356237309504880f) / 9.0f;
    int widx = c * SS + (idx & (SS - 1));
    out[idx] = fmaf(w1[widx], acc * (1.0f / 9.0f), w2[widx] * SECOND);
}

extern "C" void kernel_launch(void* const* d_in, const int* in_sizes, int n_in,
                              void* d_out, int out_size)
{
    const float* x  = (const float*)d_in[0];
    const float* w1 = (const float*)d_in[1];
    const float* w2 = (const float*)d_in[2];
    float* out = (float*)d_out;

    int total = out_size;                 // B*C*S*S = 16777216
    int threads = 256;
    int blocks = (total + threads - 1) / threads;
    pp_kernel<<<blocks, threads>>>(x, w1, w2, out);
}

// round 2
// speedup vs baseline: 1.8274x; 1.8274x over previous
#include <cuda_runtime.h>
#include <cuda_bf16.h>

// PairwisePotential1, 4 pixels/thread, float4 I/O.
// out[b,c,y,x] = w1[c,y,x] * first/9 + w2[c,y,x] * (4+4*sqrt2)/9
// first = 1 + sum of 8 exp terms; exp(-0.5*diff^2 - 0.5*d) = exp2(K*diff^2 + K*d),
// K = -0.5*log2(e). Window rooted at (y-1, x-1), zero padding.

#define S 128
#define SS (S * S)

__global__ __launch_bounds__(256) void pp_kernel(
    const float* __restrict__ x,
    const float* __restrict__ w1,
    const float* __restrict__ w2,
    float* __restrict__ out)
{
    int t  = blockIdx.x * blockDim.x + threadIdx.x;   // one thread = 4 consecutive x
    int xq = (t & 31) << 2;            // x base: 0,4,...,124
    int y  = (t >> 5) & (S - 1);
    int bc = t >> 12;                  // b*C + c
    int c  = bc & 63;

    const float* __restrict__ xb = x + (size_t)bc * SS;

    // rows y-1, y, y+1 ; columns xq-1 .. xq+4  (6 values per row)
    float r[3][6];
#pragma unroll
    for (int i = 0; i < 3; i++) {
        int ry = y - 1 + i;
        bool okY = (ry >= 0) & (ry < S);
        const float* __restrict__ row = xb + ry * S;
        float4 m = okY ? *(const float4*)(row + xq) : make_float4(0.f, 0.f, 0.f, 0.f);
        r[i][1] = m.x; r[i][2] = m.y; r[i][3] = m.z; r[i][4] = m.w;
        r[i][0] = (okY & (xq > 0))       ? __ldg(row + xq - 1) : 0.f;
        r[i][5] = (okY & (xq + 4 < S))   ? __ldg(row + xq + 4) : 0.f;
    }

    const float K  = -0.5f * 1.44269504088896340736f;   // -0.5*log2(e)
    const float L1 = K;                                  // d = 1
    const float L2 = K * 1.41421356237309504880f;        // d = sqrt(2)

    float acc[4];
#pragma unroll
    for (int p = 0; p < 4; p++) {
        const float cv = r[0][p];
        float a = 1.0f;   // (0,0) term: exp(0 - 0) = 1
        // d = 1 terms
        float d0 = cv - r[0][p + 1];
        float d1 = cv - r[0][p + 2];
        float d2 = cv - r[1][p];
        float d3 = cv - r[2][p];
        a += exp2f(fmaf(d0 * d0, K, L1));
        a += exp2f(fmaf(d1 * d1, K, L1));
        a += exp2f(fmaf(d2 * d2, K, L1));
        a += exp2f(fmaf(d3 * d3, K, L1));
        // d = sqrt(2) terms
        float e0 = cv - r[1][p + 1];
        float e1 = cv - r[1][p + 2];
        float e2 = cv - r[2][p + 1];
        float e3 = cv - r[2][p + 2];
        a += exp2f(fmaf(e0 * e0, K, L2));
        a += exp2f(fmaf(e1 * e1, K, L2));
        a += exp2f(fmaf(e2 * e2, K, L2));
        a += exp2f(fmaf(e3 * e3, K, L2));
        acc[p] = a;
    }

    const float INV9   = 1.0f / 9.0f;
    const float SECOND = (4.0f + 4.0f * 1.41421356237309504880f) / 9.0f;

    int wbase = c * SS + y * S + xq;
    float4 a1 = *(const float4*)(w1 + wbase);
    float4 a2 = *(const float4*)(w2 + wbase);

    float4 o;
    o.x = fmaf(a1.x, acc[0] * INV9, a2.x * SECOND);
    o.y = fmaf(a1.y, acc[1] * INV9, a2.y * SECOND);
    o.z = fmaf(a1.z, acc[2] * INV9, a2.z * SECOND);
    o.w = fmaf(a1.w, acc[3] * INV9, a2.w * SECOND);

    ((float4*)out)[t] = o;
}

extern "C" void kernel_launch(void* const* d_in, const int* in_sizes, int n_in,
                              void* d_out, int out_size)
{
    const float* x  = (const float*)d_in[0];
    const float* w1 = (const float*)d_in[1];
    const float* w2 = (const float*)d_in[2];
    float* out = (float*)d_out;

    int total4 = out_size >> 2;          // 4 pixels per thread
    int threads = 256;
    int blocks = (total4 + threads - 1) / threads;
    pp_kernel<<<blocks, threads>>>(x, w1, w2, out);
}

// round 3
// speedup vs baseline: 2.0177x; 1.1042x over previous
#include <cuda_runtime.h>
#include <cuda_bf16.h>

// PairwisePotential1 — 8 px/thread, pixel-pairs packed with f32x2 PTX ops.
// out = w1 * first/9 + w2 * (4+4*sqrt2)/9
// first = 1 + sum_{8 offsets} exp2(K*diff^2 + K*d),  K = -0.5*log2(e),
// window rows y-1..y+1, center col x-1, zero padding.

#define S 128
#define SS (S * S)

typedef unsigned long long u64;

__device__ __forceinline__ u64 pk(float lo, float hi) {
    u64 r; asm("mov.b64 %0, {%1, %2};" : "=l"(r) : "f"(lo), "f"(hi)); return r;
}
__device__ __forceinline__ void upk(u64 v, float& lo, float& hi) {
    asm("mov.b64 {%0, %1}, %2;" : "=f"(lo), "=f"(hi) : "l"(v));
}
__device__ __forceinline__ u64 fma2(u64 a, u64 b, u64 c) {
    u64 r; asm("fma.rn.f32x2 %0, %1, %2, %3;" : "=l"(r) : "l"(a), "l"(b), "l"(c)); return r;
}
__device__ __forceinline__ u64 mul2(u64 a, u64 b) {
    u64 r; asm("mul.rn.f32x2 %0, %1, %2;" : "=l"(r) : "l"(a), "l"(b)); return r;
}
__device__ __forceinline__ u64 add2(u64 a, u64 b) {
    u64 r; asm("add.rn.f32x2 %0, %1, %2;" : "=l"(r) : "l"(a), "l"(b)); return r;
}
__device__ __forceinline__ float ex2(float x) {
    float r; asm("ex2.approx.f32 %0, %1;" : "=f"(r) : "f"(x)); return r;
}

__global__ __launch_bounds__(256) void pp_kernel(
    const float* __restrict__ x,
    const float* __restrict__ w1,
    const float* __restrict__ w2,
    float* __restrict__ out)
{
    int t  = blockIdx.x * blockDim.x + threadIdx.x;  // one thread = 8 consecutive x
    int xo = (t & 15) << 3;           // 0,8,...,120
    int y  = (t >> 4) & (S - 1);
    int bc = t >> 11;                 // b*C + c
    int c  = bc & 63;

    const float* __restrict__ xb = x + (size_t)bc * SS;

    // Load 3 rows (y-1, y, y+1), columns xo-1 .. xo+8 (10 values each), zero OOB.
    float v[3][10];
#pragma unroll
    for (int i = 0; i < 3; i++) {
        int ry = y - 1 + i;
        bool okY = (ry >= 0) & (ry < S);
        const float* __restrict__ rp = xb + ry * S + xo;
        float4 A = okY ? *(const float4*)(rp)     : make_float4(0.f, 0.f, 0.f, 0.f);
        float4 B = okY ? *(const float4*)(rp + 4) : make_float4(0.f, 0.f, 0.f, 0.f);
        v[i][0] = (okY & (xo > 0))     ? __ldg(rp - 1) : 0.f;
        v[i][1] = A.x; v[i][2] = A.y; v[i][3] = A.z; v[i][4] = A.w;
        v[i][5] = B.x; v[i][6] = B.y; v[i][7] = B.z; v[i][8] = B.w;
        v[i][9] = (okY & (xo + 8 < S)) ? __ldg(rp + 8) : 0.f;
    }

    // Pack pairs per row:
    //   E[q] = (v[2q], v[2q+1])  q=0..4   (cross-register packs)
    //   O[q] = (v[2q+1], v[2q+2]) q=0..3  (float4 lane pairs)
    u64 E[3][5], O[3][4];
#pragma unroll
    for (int i = 0; i < 3; i++) {
#pragma unroll
        for (int q = 0; q < 5; q++) E[i][q] = pk(v[i][2 * q], v[i][2 * q + 1]);
#pragma unroll
        for (int q = 0; q < 4; q++) O[i][q] = pk(v[i][2 * q + 1], v[i][2 * q + 2]);
    }

    const float Kf  = -0.5f * 1.44269504088896340736f;   // -0.5*log2(e)
    const float L1f = Kf;                                 // d = 1
    const float L2f = Kf * 1.41421356237309504880f;       // d = sqrt(2)
    const u64 K2   = pk(Kf, Kf);
    const u64 LL1  = pk(L1f, L1f);
    const u64 LL2  = pk(L2f, L2f);
    const u64 NEG1 = pk(-1.0f, -1.0f);
    const u64 ONE2 = pk(1.0f, 1.0f);

    const float INV9   = 1.0f / 9.0f;
    const float SECOND = (4.0f + 4.0f * 1.41421356237309504880f) / 9.0f;
    const u64 INV9_2 = pk(INV9, INV9);
    const u64 SEC2   = pk(SECOND, SECOND);

    int wbase = c * SS + y * S + xo;
    float4 w1a = *(const float4*)(w1 + wbase);
    float4 w1b = *(const float4*)(w1 + wbase + 4);
    float4 w2a = *(const float4*)(w2 + wbase);
    float4 w2b = *(const float4*)(w2 + wbase + 4);

    float o[8];
#pragma unroll
    for (int q = 0; q < 4; q++) {       // pixel pair (2q, 2q+1)
        u64 cv = E[0][q];
        u64 acc = ONE2;                  // (0,0) term = 1 for both pixels

        // 8 packed terms: d=1 -> O0[q], E0[q+1], E1[q], E2[q]
        //                 d=sqrt2 -> O1[q], E1[q+1], O2[q], E2[q+1]
        u64 n, d, s, a; float alo, ahi;
#define TERM(NP, LL)                                        \
        n = (NP);                                           \
        d = fma2(n, NEG1, cv);                              \
        s = mul2(d, d);                                     \
        a = fma2(s, K2, LL);                                \
        upk(a, alo, ahi);                                   \
        acc = add2(acc, pk(ex2(alo), ex2(ahi)));

        TERM(O[0][q],     LL1)
        TERM(E[0][q + 1], LL1)
        TERM(E[1][q],     LL1)
        TERM(E[2][q],     LL1)
        TERM(O[1][q],     LL2)
        TERM(E[1][q + 1], LL2)
        TERM(O[2][q],     LL2)
        TERM(E[2][q + 1], LL2)
#undef TERM

        // out_pair = w1 * acc/9 + w2 * SECOND
        u64 w1p = (q == 0) ? pk(w1a.x, w1a.y) : (q == 1) ? pk(w1a.z, w1a.w)
                 : (q == 2) ? pk(w1b.x, w1b.y) : pk(w1b.z, w1b.w);
        u64 w2p = (q == 0) ? pk(w2a.x, w2a.y) : (q == 1) ? pk(w2a.z, w2a.w)
                 : (q == 2) ? pk(w2b.x, w2b.y) : pk(w2b.z, w2b.w);
        u64 res = fma2(w1p, mul2(acc, INV9_2), mul2(w2p, SEC2));
        upk(res, o[2 * q], o[2 * q + 1]);
    }

    float4* op = (float4*)(out + (size_t)t * 8);
    op[0] = make_float4(o[0], o[1], o[2], o[3]);
    op[1] = make_float4(o[4], o[5], o[6], o[7]);
}

extern "C" void kernel_launch(void* const* d_in, const int* in_sizes, int n_in,
                              void* d_out, int out_size)
{
    const float* x  = (const float*)d_in[0];
    const float* w1 = (const float*)d_in[1];
    const float* w2 = (const float*)d_in[2];
    float* out = (float*)d_out;

    int total8 = out_size >> 3;          // 8 pixels per thread
    int threads = 256;
    int blocks = (total8 + threads - 1) / threads;
    pp_kernel<<<blocks, threads>>>(x, w1, w2, out);
}